// round 2
// baseline (speedup 1.0000x reference)
#include <cuda_runtime.h>

#define BB 16
#define CC 128
#define HEAD 8
#define DKK 16
#define NNN 2500
#define LLL 12
#define NPOS (NNN*LLL)            /* 30000 */
#define TP 128                    /* positions per tile */
#define NT ((NPOS + TP - 1)/TP)   /* 235 */
#define KV_PITCH 2052             /* padded per-l pitch (floats) */

typedef unsigned long long u64;

// ---------------- device scratch (allocation-free: __device__ globals) ----------------
__device__ __align__(16) float g_WqT[CC*CC];
__device__ __align__(16) float g_WvT[CC*CC];
__device__ __align__(16) float g_WcT[CC*CC];
__device__ __align__(16) float g_key[HEAD*LLL*NNN*DKK];      // softmaxed key bank
__device__ __align__(16) float g_kv[BB*LLL*HEAD*DKK*DKK];    // 393216 floats
__device__ __align__(16) float g_q[(size_t)BB*CC*NPOS];      // softmaxed q
__device__ __align__(16) float g_o[(size_t)BB*CC*NPOS];      // o = q @ kv

// ---------------- packed f32x2 helpers ----------------
__device__ __forceinline__ u64 fma2(u64 a, u64 b, u64 c) {
    u64 d;
    asm("fma.rn.f32x2 %0, %1, %2, %3;" : "=l"(d) : "l"(a), "l"(b), "l"(c));
    return d;
}
__device__ __forceinline__ u64 pack2(float x, float y) {
    u64 d;
    asm("mov.b64 %0, {%1, %2};" : "=l"(d) : "f"(x), "f"(y));
    return d;
}
__device__ __forceinline__ float2 unpack2(u64 v) {
    float2 f;
    asm("mov.b64 {%0, %1}, %2;" : "=f"(f.x), "=f"(f.y) : "l"(v));
    return f;
}

// ---------------- 128x128x128 GEMM microkernel, weights from GLOBAL ----------------
// wg: [k][o] pitch 128 in global (pre-transposed, L1-resident, broadcast reads).
// xs: [k][p] pitch 128 in smem.
// Thread (ty,tx): o in [o0,o0+8), p in [pt,pt+8) as 8x4 f32x2 accumulators.
__device__ __forceinline__ void gemm128g(const float* __restrict__ wg,
                                         const float* __restrict__ xs,
                                         u64 acc[8][4], int o0, int pt) {
#pragma unroll
    for (int j = 0; j < 8; j++)
#pragma unroll
        for (int i = 0; i < 4; i++) acc[j][i] = 0ull;

#pragma unroll 4
    for (int k = 0; k < 128; k++) {
        float4 a0 = __ldg((const float4*)(wg + k*128 + o0));
        float4 a1 = __ldg((const float4*)(wg + k*128 + o0 + 4));
        ulonglong2 b0 = *(const ulonglong2*)(xs + k*128 + pt);
        ulonglong2 b1 = *(const ulonglong2*)(xs + k*128 + pt + 4);
        u64 bb[4]; bb[0]=b0.x; bb[1]=b0.y; bb[2]=b1.x; bb[3]=b1.y;
        float av[8]; av[0]=a0.x; av[1]=a0.y; av[2]=a0.z; av[3]=a0.w;
                     av[4]=a1.x; av[5]=a1.y; av[6]=a1.z; av[7]=a1.w;
#pragma unroll
        for (int j = 0; j < 8; j++) {
            u64 aj = pack2(av[j], av[j]);
#pragma unroll
            for (int i = 0; i < 4; i++) acc[j][i] = fma2(aj, bb[i], acc[j][i]);
        }
    }
}

// ---------------- prep kernels ----------------
__global__ void k_prep_w(const float* __restrict__ Wq, const float* __restrict__ Wv,
                         const float* __restrict__ Wc) {
    const float* src = (blockIdx.x == 0) ? Wq : (blockIdx.x == 1) ? Wv : Wc;
    float* dst = (blockIdx.x == 0) ? g_WqT : (blockIdx.x == 1) ? g_WvT : g_WcT;
    for (int i = threadIdx.x; i < CC*CC; i += 256) {
        int o = i >> 7, c = i & 127;
        dst[c*128 + o] = src[i];
    }
}

__global__ void k_key(const float* __restrict__ s_bank) {
    int r = blockIdx.x * 256 + threadIdx.x;           // (h,l,n) row
    if (r >= HEAD*LLL*NNN) return;
    const float4* src = (const float4*)(s_bank + (size_t)r * 16);
    float4 v0 = src[0], v1 = src[1], v2 = src[2], v3 = src[3];
    float v[16] = {v0.x,v0.y,v0.z,v0.w, v1.x,v1.y,v1.z,v1.w,
                   v2.x,v2.y,v2.z,v2.w, v3.x,v3.y,v3.z,v3.w};
    float mx = v[0];
#pragma unroll
    for (int i = 1; i < 16; i++) mx = fmaxf(mx, v[i]);
    float s = 0.f;
#pragma unroll
    for (int i = 0; i < 16; i++) { v[i] = __expf(0.25f * (v[i] - mx)); s += v[i]; }
    float inv = 1.f / s;
#pragma unroll
    for (int i = 0; i < 16; i++) v[i] *= inv;
    float4* dst = (float4*)(g_key + (size_t)r * 16);
    dst[0] = make_float4(v[0],v[1],v[2],v[3]);
    dst[1] = make_float4(v[4],v[5],v[6],v[7]);
    dst[2] = make_float4(v[8],v[9],v[10],v[11]);
    dst[3] = make_float4(v[12],v[13],v[14],v[15]);
}

__global__ void k_zero_kv() {
    int i = blockIdx.x * 256 + threadIdx.x;
    ((float4*)g_kv)[i] = make_float4(0.f, 0.f, 0.f, 0.f);
}

// ---------------- pass A: q = softmax(relu(Wq x + bq)) -> g_q ; kv += key^T v ----------------
#define SMEM_A_BYTES (16384 * 4)
__global__ void __launch_bounds__(256, 2)
kernelA(const float* __restrict__ x, const float* __restrict__ bq, const float* __restrict__ bv) {
    extern __shared__ float xs[];   // [c][p] 16384 floats

    int b = blockIdx.y, tile = blockIdx.x;
    int p0 = tile * TP;
    int pc = min(TP, NPOS - p0);
    int tid = threadIdx.x;

    // load x tile (coalesced)
    const float* xb = x + ((size_t)b * CC) * NPOS + p0;
    if (pc == TP) {
        for (int i = tid; i < CC * TP / 4; i += 256) {
            int c = i >> 5, p4 = i & 31;
            ((float4*)xs)[c*32 + p4] = ((const float4*)(xb + (size_t)c * NPOS))[p4];
        }
    } else {
        for (int i = tid; i < CC * TP; i += 256) {
            int c = i >> 7, p = i & 127;
            xs[i] = (p < pc) ? xb[(size_t)c * NPOS + p] : 0.f;
        }
    }
    __syncthreads();

    int ty = tid >> 4, tx = tid & 15;
    int o0 = ty * 8, pt = tx * 8;
    u64 acc[8][4];
    float r[8][8];

    // ---- Q GEMM (weights from L1/global) ----
    gemm128g(g_WqT, xs, acc, o0, pt);
#pragma unroll
    for (int j = 0; j < 8; j++) {
        float bj = __ldg(bq + o0 + j);
#pragma unroll
        for (int i = 0; i < 4; i++) {
            float2 f = unpack2(acc[j][i]);
            r[j][2*i]     = fmaxf(f.x + bj, 0.f);
            r[j][2*i + 1] = fmaxf(f.y + bj, 0.f);
        }
    }

    // ---- softmax over 16-channel head group: ty pair (2h, 2h+1) = lane ^ 16 ----
#pragma unroll
    for (int p = 0; p < 8; p++) {
        float m = r[0][p];
#pragma unroll
        for (int j = 1; j < 8; j++) m = fmaxf(m, r[j][p]);
        m = fmaxf(m, __shfl_xor_sync(0xffffffffu, m, 16));
        float s = 0.f;
#pragma unroll
        for (int j = 0; j < 8; j++) { r[j][p] = __expf(0.25f * (r[j][p] - m)); s += r[j][p]; }
        s += __shfl_xor_sync(0xffffffffu, s, 16);
        float inv = 1.f / s;
#pragma unroll
        for (int j = 0; j < 8; j++) r[j][p] *= inv;
    }

    // ---- write q_soft directly from regs ----
    float* qb = g_q + ((size_t)b * CC) * NPOS + p0;
    if (pc == TP) {
#pragma unroll
        for (int j = 0; j < 8; j++) {
            float* row = qb + (size_t)(o0 + j) * NPOS + pt;
            ((float4*)row)[0] = make_float4(r[j][0], r[j][1], r[j][2], r[j][3]);
            ((float4*)row)[1] = make_float4(r[j][4], r[j][5], r[j][6], r[j][7]);
        }
    } else {
#pragma unroll
        for (int j = 0; j < 8; j++) {
            float* row = qb + (size_t)(o0 + j) * NPOS;
#pragma unroll
            for (int i = 0; i < 8; i++)
                if (pt + i < pc) row[pt + i] = r[j][i];
        }
    }

    // ---- V GEMM ----
    gemm128g(g_WvT, xs, acc, o0, pt);
#pragma unroll
    for (int j = 0; j < 8; j++) {
        float bj = __ldg(bv + o0 + j);
#pragma unroll
        for (int i = 0; i < 4; i++) {
            float2 f = unpack2(acc[j][i]);
            r[j][2*i]     = fmaxf(f.x + bj, 0.f);
            r[j][2*i + 1] = fmaxf(f.y + bj, 0.f);
        }
    }
    __syncthreads();   // everyone done READING xs
    // write v into xs (reuse)
#pragma unroll
    for (int j = 0; j < 8; j++) {
        float* row = xs + (o0 + j) * 128 + pt;
        ((float4*)row)[0] = make_float4(r[j][0], r[j][1], r[j][2], r[j][3]);
        ((float4*)row)[1] = make_float4(r[j][4], r[j][5], r[j][6], r[j][7]);
    }
    __syncthreads();

    // ---- kv accumulation: warp = head; lane -> (x, y-block of 8) ----
    {
        int w = tid >> 5, lane = tid & 31;
        int h = w;
        int xk = lane & 15, yb = (lane >> 4) * 8;
        const float* keyh = g_key + (size_t)h * (LLL * NNN * DKK);
        for (int l = 0; l < LLL; l++) {
            float a8[8];
#pragma unroll
            for (int j = 0; j < 8; j++) a8[j] = 0.f;
            int s = ((l - p0) % 12 + 12) % 12;
            for (int p = s; p < pc; p += 12) {
                int P = p0 + p;
                int n = P / 12;
                float kx = keyh[((size_t)l * NNN + n) * DKK + xk];
                const float* vcol = xs + (h * 16 + yb) * 128 + p;
#pragma unroll
                for (int j = 0; j < 8; j++) a8[j] = fmaf(kx, vcol[j * 128], a8[j]);
            }
            float* kvp = g_kv + ((((size_t)b * LLL + l) * HEAD + h) * DKK + xk) * DKK + yb;
#pragma unroll
            for (int j = 0; j < 8; j++) atomicAdd(kvp + j, a8[j]);
        }
    }
}

// ---------------- pass B1: o = q @ kv -> g_o ----------------
#define TPB1 256
#define NTB1 ((NPOS + TPB1 - 1)/TPB1)    /* 118 */
#define SMEM_B1_BYTES (LLL * KV_PITCH * 4)
__global__ void __launch_bounds__(256, 2)
kernelB1() {
    extern __shared__ float kvs[];   // kv[l][h][x][y], per-l pitch KV_PITCH

    int b = blockIdx.y;
    int P = blockIdx.x * TPB1 + threadIdx.x;
    int tid = threadIdx.x;

    const float* kvb = g_kv + (size_t)b * (LLL * HEAD * DKK * DKK);
    for (int i = tid; i < LLL * HEAD * DKK * DKK; i += 256) {
        int l = i >> 11, rr = i & 2047;
        kvs[l * KV_PITCH + rr] = kvb[i];
    }
    __syncthreads();

    if (P >= NPOS) return;
    int l = P % 12;
    const float* kvl = kvs + l * KV_PITCH;
    const float* qb = g_q + ((size_t)b * CC) * NPOS + P;
    float* ob = g_o + ((size_t)b * CC) * NPOS + P;

#pragma unroll
    for (int h = 0; h < HEAD; h++) {
        const float* kvh = kvl + h * 256;
        float s16[16];
#pragma unroll
        for (int y = 0; y < 16; y++) s16[y] = 0.f;
#pragma unroll
        for (int xq = 0; xq < 16; xq++) {
            float qv = qb[(size_t)(h * 16 + xq) * NPOS];
            const float4* kr = (const float4*)(kvh + xq * 16);
            float4 k0 = kr[0], k1 = kr[1], k2 = kr[2], k3 = kr[3];
            s16[0]  = fmaf(qv, k0.x, s16[0]);  s16[1]  = fmaf(qv, k0.y, s16[1]);
            s16[2]  = fmaf(qv, k0.z, s16[2]);  s16[3]  = fmaf(qv, k0.w, s16[3]);
            s16[4]  = fmaf(qv, k1.x, s16[4]);  s16[5]  = fmaf(qv, k1.y, s16[5]);
            s16[6]  = fmaf(qv, k1.z, s16[6]);  s16[7]  = fmaf(qv, k1.w, s16[7]);
            s16[8]  = fmaf(qv, k2.x, s16[8]);  s16[9]  = fmaf(qv, k2.y, s16[9]);
            s16[10] = fmaf(qv, k2.z, s16[10]); s16[11] = fmaf(qv, k2.w, s16[11]);
            s16[12] = fmaf(qv, k3.x, s16[12]); s16[13] = fmaf(qv, k3.y, s16[13]);
            s16[14] = fmaf(qv, k3.z, s16[14]); s16[15] = fmaf(qv, k3.w, s16[15]);
        }
#pragma unroll
        for (int y = 0; y < 16; y++) ob[(size_t)(h * 16 + y) * NPOS] = s16[y];
    }
}

// ---------------- pass B2: out = relu(Wc o + bc) ----------------
#define SMEM_B2_BYTES (16384 * 4)
__global__ void __launch_bounds__(256, 2)
kernelB2(const float* __restrict__ bc, float* __restrict__ out) {
    extern __shared__ float os[];   // [c][p]

    int b = blockIdx.y, tile = blockIdx.x;
    int p0 = tile * TP;
    int pc = min(TP, NPOS - p0);
    int tid = threadIdx.x;

    const float* ob0 = g_o + ((size_t)b * CC) * NPOS + p0;
    if (pc == TP) {
        for (int i = tid; i < CC * TP / 4; i += 256) {
            int c = i >> 5, p4 = i & 31;
            ((float4*)os)[c*32 + p4] = ((const float4*)(ob0 + (size_t)c * NPOS))[p4];
        }
    } else {
        for (int i = tid; i < CC * TP; i += 256) {
            int c = i >> 7, p = i & 127;
            os[i] = (p < pc) ? ob0[(size_t)c * NPOS + p] : 0.f;
        }
    }
    __syncthreads();

    int ty = tid >> 4, tx = tid & 15;
    int o0 = ty * 8, pt = tx * 8;
    u64 acc[8][4];
    gemm128g(g_WcT, os, acc, o0, pt);

    float* ob = out + ((size_t)b * CC) * NPOS + p0;
    if (pc == TP) {
#pragma unroll
        for (int j = 0; j < 8; j++) {
            float bj = __ldg(bc + o0 + j);
            float* row = ob + (size_t)(o0 + j) * NPOS + pt;
            float2 f0 = unpack2(acc[j][0]), f1 = unpack2(acc[j][1]);
            float2 f2 = unpack2(acc[j][2]), f3 = unpack2(acc[j][3]);
            ((float4*)row)[0] = make_float4(fmaxf(f0.x + bj, 0.f), fmaxf(f0.y + bj, 0.f),
                                            fmaxf(f1.x + bj, 0.f), fmaxf(f1.y + bj, 0.f));
            ((float4*)row)[1] = make_float4(fmaxf(f2.x + bj, 0.f), fmaxf(f2.y + bj, 0.f),
                                            fmaxf(f3.x + bj, 0.f), fmaxf(f3.y + bj, 0.f));
        }
    } else {
#pragma unroll
        for (int j = 0; j < 8; j++) {
            float bj = __ldg(bc + o0 + j);
            float* row = ob + (size_t)(o0 + j) * NPOS;
#pragma unroll
            for (int i = 0; i < 4; i++) {
                float2 f = unpack2(acc[j][i]);
                int pA = pt + 2*i, pB = pt + 2*i + 1;
                if (pA < pc) row[pA] = fmaxf(f.x + bj, 0.f);
                if (pB < pc) row[pB] = fmaxf(f.y + bj, 0.f);
            }
        }
    }
}

// ---------------- launch ----------------
extern "C" void kernel_launch(void* const* d_in, const int* in_sizes, int n_in,
                              void* d_out, int out_size) {
    (void)in_sizes; (void)n_in; (void)out_size;
    const float* x      = (const float*)d_in[0];
    const float* Wq     = (const float*)d_in[1];
    const float* bq     = (const float*)d_in[2];
    const float* Wv     = (const float*)d_in[3];
    const float* bv     = (const float*)d_in[4];
    const float* Wc     = (const float*)d_in[5];
    const float* bc     = (const float*)d_in[6];
    const float* s_bank = (const float*)d_in[7];
    float* out = (float*)d_out;

    cudaFuncSetAttribute(kernelA,  cudaFuncAttributeMaxDynamicSharedMemorySize, SMEM_A_BYTES);
    cudaFuncSetAttribute(kernelB1, cudaFuncAttributeMaxDynamicSharedMemorySize, SMEM_B1_BYTES);
    cudaFuncSetAttribute(kernelB2, cudaFuncAttributeMaxDynamicSharedMemorySize, SMEM_B2_BYTES);

    k_prep_w<<<3, 256>>>(Wq, Wv, Wc);
    k_key<<<(HEAD*LLL*NNN + 255) / 256, 256>>>(s_bank);
    k_zero_kv<<<(BB*LLL*HEAD*DKK*DKK/4) / 256, 256>>>();
    kernelA<<<dim3(NT, BB), 256, SMEM_A_BYTES>>>(x, bq, bv);
    kernelB1<<<dim3(NTB1, BB), 256, SMEM_B1_BYTES>>>();
    kernelB2<<<dim3(NT, BB), 256, SMEM_B2_BYTES>>>(bc, out);
}

// round 3
// speedup vs baseline: 1.5348x; 1.5348x over previous
#include <cuda_runtime.h>

#define BB 16
#define CC 128
#define HEAD 8
#define DKK 16
#define NNN 2500
#define LLL 12
#define NPOS (NNN*LLL)            /* 30000 */
#define TP 128                    /* positions per tile */
#define NT ((NPOS + TP - 1)/TP)   /* 235 */
#define KV_PITCH 2052             /* padded per-l pitch (floats) */

typedef unsigned long long u64;

// ---------------- device scratch (allocation-free: __device__ globals) ----------------
__device__ __align__(16) float g_WqT[CC*CC];
__device__ __align__(16) float g_WvT[CC*CC];
__device__ __align__(16) float g_WcT[CC*CC];
__device__ __align__(16) float g_key[HEAD*LLL*NNN*DKK];      // softmaxed key bank
__device__ __align__(16) float g_kv[BB*LLL*HEAD*DKK*DKK];    // 393216 floats
__device__ __align__(16) float g_q[(size_t)BB*CC*NPOS];      // softmaxed q
__device__ __align__(16) float g_o[(size_t)BB*CC*NPOS];      // o = q @ kv

// ---------------- packed f32x2 helpers ----------------
__device__ __forceinline__ u64 fma2(u64 a, u64 b, u64 c) {
    u64 d;
    asm("fma.rn.f32x2 %0, %1, %2, %3;" : "=l"(d) : "l"(a), "l"(b), "l"(c));
    return d;
}
__device__ __forceinline__ u64 pack2(float x, float y) {
    u64 d;
    asm("mov.b64 %0, {%1, %2};" : "=l"(d) : "f"(x), "f"(y));
    return d;
}
__device__ __forceinline__ float2 unpack2(u64 v) {
    float2 f;
    asm("mov.b64 {%0, %1}, %2;" : "=f"(f.x), "=f"(f.y) : "l"(v));
    return f;
}

// ---------------- 128x128x128 GEMM microkernel, weights from GLOBAL ----------------
// wg: [k][o] pitch 128 in global (pre-transposed, L1-resident, broadcast reads).
// xs: [k][p] pitch 128 in smem.
// Thread (ty,tx): o in [o0,o0+8), p in [pt,pt+8) as 8x4 f32x2 accumulators.
__device__ __forceinline__ void gemm128g(const float* __restrict__ wg,
                                         const float* __restrict__ xs,
                                         u64 acc[8][4], int o0, int pt) {
#pragma unroll
    for (int j = 0; j < 8; j++)
#pragma unroll
        for (int i = 0; i < 4; i++) acc[j][i] = 0ull;

#pragma unroll 4
    for (int k = 0; k < 128; k++) {
        float4 a0 = __ldg((const float4*)(wg + k*128 + o0));
        float4 a1 = __ldg((const float4*)(wg + k*128 + o0 + 4));
        ulonglong2 b0 = *(const ulonglong2*)(xs + k*128 + pt);
        ulonglong2 b1 = *(const ulonglong2*)(xs + k*128 + pt + 4);
        u64 bb[4]; bb[0]=b0.x; bb[1]=b0.y; bb[2]=b1.x; bb[3]=b1.y;
        float av[8]; av[0]=a0.x; av[1]=a0.y; av[2]=a0.z; av[3]=a0.w;
                     av[4]=a1.x; av[5]=a1.y; av[6]=a1.z; av[7]=a1.w;
#pragma unroll
        for (int j = 0; j < 8; j++) {
            u64 aj = pack2(av[j], av[j]);
#pragma unroll
            for (int i = 0; i < 4; i++) acc[j][i] = fma2(aj, bb[i], acc[j][i]);
        }
    }
}

// ---------------- prep kernels ----------------
__global__ void k_prep_w(const float* __restrict__ Wq, const float* __restrict__ Wv,
                         const float* __restrict__ Wc) {
    const float* src = (blockIdx.x == 0) ? Wq : (blockIdx.x == 1) ? Wv : Wc;
    float* dst = (blockIdx.x == 0) ? g_WqT : (blockIdx.x == 1) ? g_WvT : g_WcT;
    for (int i = threadIdx.x; i < CC*CC; i += 256) {
        int o = i >> 7, c = i & 127;
        dst[c*128 + o] = src[i];
    }
}

__global__ void k_key(const float* __restrict__ s_bank) {
    int r = blockIdx.x * 256 + threadIdx.x;           // (h,l,n) row
    if (r >= HEAD*LLL*NNN) return;
    const float4* src = (const float4*)(s_bank + (size_t)r * 16);
    float4 v0 = src[0], v1 = src[1], v2 = src[2], v3 = src[3];
    float v[16] = {v0.x,v0.y,v0.z,v0.w, v1.x,v1.y,v1.z,v1.w,
                   v2.x,v2.y,v2.z,v2.w, v3.x,v3.y,v3.z,v3.w};
    float mx = v[0];
#pragma unroll
    for (int i = 1; i < 16; i++) mx = fmaxf(mx, v[i]);
    float s = 0.f;
#pragma unroll
    for (int i = 0; i < 16; i++) { v[i] = __expf(0.25f * (v[i] - mx)); s += v[i]; }
    float inv = 1.f / s;
#pragma unroll
    for (int i = 0; i < 16; i++) v[i] *= inv;
    float4* dst = (float4*)(g_key + (size_t)r * 16);
    dst[0] = make_float4(v[0],v[1],v[2],v[3]);
    dst[1] = make_float4(v[4],v[5],v[6],v[7]);
    dst[2] = make_float4(v[8],v[9],v[10],v[11]);
    dst[3] = make_float4(v[12],v[13],v[14],v[15]);
}

__global__ void k_zero_kv() {
    int i = blockIdx.x * 256 + threadIdx.x;
    ((float4*)g_kv)[i] = make_float4(0.f, 0.f, 0.f, 0.f);
}

// ---------------- pass A: q = softmax(relu(Wq x + bq)) -> g_q ; kv += key^T v ----------------
#define SMEM_A_BYTES (16384 * 4)
__global__ void __launch_bounds__(256, 2)
kernelA(const float* __restrict__ x, const float* __restrict__ bq, const float* __restrict__ bv) {
    extern __shared__ float xs[];   // [c][p] 16384 floats

    int b = blockIdx.y, tile = blockIdx.x;
    int p0 = tile * TP;
    int pc = min(TP, NPOS - p0);
    int tid = threadIdx.x;

    // load x tile (coalesced)
    const float* xb = x + ((size_t)b * CC) * NPOS + p0;
    if (pc == TP) {
        for (int i = tid; i < CC * TP / 4; i += 256) {
            int c = i >> 5, p4 = i & 31;
            ((float4*)xs)[c*32 + p4] = ((const float4*)(xb + (size_t)c * NPOS))[p4];
        }
    } else {
        for (int i = tid; i < CC * TP; i += 256) {
            int c = i >> 7, p = i & 127;
            xs[i] = (p < pc) ? xb[(size_t)c * NPOS + p] : 0.f;
        }
    }
    __syncthreads();

    int ty = tid >> 4, tx = tid & 15;
    int o0 = ty * 8, pt = tx * 8;
    u64 acc[8][4];
    float r[8][8];

    // ---- Q GEMM (weights from L1/global) ----
    gemm128g(g_WqT, xs, acc, o0, pt);
#pragma unroll
    for (int j = 0; j < 8; j++) {
        float bj = __ldg(bq + o0 + j);
#pragma unroll
        for (int i = 0; i < 4; i++) {
            float2 f = unpack2(acc[j][i]);
            r[j][2*i]     = fmaxf(f.x + bj, 0.f);
            r[j][2*i + 1] = fmaxf(f.y + bj, 0.f);
        }
    }

    // ---- softmax over 16-channel head group: ty pair (2h, 2h+1) = lane ^ 16 ----
#pragma unroll
    for (int p = 0; p < 8; p++) {
        float m = r[0][p];
#pragma unroll
        for (int j = 1; j < 8; j++) m = fmaxf(m, r[j][p]);
        m = fmaxf(m, __shfl_xor_sync(0xffffffffu, m, 16));
        float s = 0.f;
#pragma unroll
        for (int j = 0; j < 8; j++) { r[j][p] = __expf(0.25f * (r[j][p] - m)); s += r[j][p]; }
        s += __shfl_xor_sync(0xffffffffu, s, 16);
        float inv = 1.f / s;
#pragma unroll
        for (int j = 0; j < 8; j++) r[j][p] *= inv;
    }

    // ---- write q_soft directly from regs ----
    float* qb = g_q + ((size_t)b * CC) * NPOS + p0;
    if (pc == TP) {
#pragma unroll
        for (int j = 0; j < 8; j++) {
            float* row = qb + (size_t)(o0 + j) * NPOS + pt;
            ((float4*)row)[0] = make_float4(r[j][0], r[j][1], r[j][2], r[j][3]);
            ((float4*)row)[1] = make_float4(r[j][4], r[j][5], r[j][6], r[j][7]);
        }
    } else {
#pragma unroll
        for (int j = 0; j < 8; j++) {
            float* row = qb + (size_t)(o0 + j) * NPOS;
#pragma unroll
            for (int i = 0; i < 8; i++)
                if (pt + i < pc) row[pt + i] = r[j][i];
        }
    }

    // ---- V GEMM ----
    gemm128g(g_WvT, xs, acc, o0, pt);
#pragma unroll
    for (int j = 0; j < 8; j++) {
        float bj = __ldg(bv + o0 + j);
#pragma unroll
        for (int i = 0; i < 4; i++) {
            float2 f = unpack2(acc[j][i]);
            r[j][2*i]     = fmaxf(f.x + bj, 0.f);
            r[j][2*i + 1] = fmaxf(f.y + bj, 0.f);
        }
    }
    __syncthreads();   // everyone done READING xs
    // write v into xs (reuse)
#pragma unroll
    for (int j = 0; j < 8; j++) {
        float* row = xs + (o0 + j) * 128 + pt;
        ((float4*)row)[0] = make_float4(r[j][0], r[j][1], r[j][2], r[j][3]);
        ((float4*)row)[1] = make_float4(r[j][4], r[j][5], r[j][6], r[j][7]);
    }
    __syncthreads();

    // ---- kv accumulation: warp = head; lane -> (x, y-block of 8) ----
    {
        int w = tid >> 5, lane = tid & 31;
        int h = w;
        int xk = lane & 15, yb = (lane >> 4) * 8;
        const float* keyh = g_key + (size_t)h * (LLL * NNN * DKK);
        for (int l = 0; l < LLL; l++) {
            float a8[8];
#pragma unroll
            for (int j = 0; j < 8; j++) a8[j] = 0.f;
            int s = ((l - p0) % 12 + 12) % 12;
            for (int p = s; p < pc; p += 12) {
                int P = p0 + p;
                int n = P / 12;
                float kx = keyh[((size_t)l * NNN + n) * DKK + xk];
                const float* vcol = xs + (h * 16 + yb) * 128 + p;
#pragma unroll
                for (int j = 0; j < 8; j++) a8[j] = fmaf(kx, vcol[j * 128], a8[j]);
            }
            float* kvp = g_kv + ((((size_t)b * LLL + l) * HEAD + h) * DKK + xk) * DKK + yb;
#pragma unroll
            for (int j = 0; j < 8; j++) atomicAdd(kvp + j, a8[j]);
        }
    }
}

// ---------------- pass B1: o = q @ kv -> g_o ----------------
#define TPB1 256
#define NTB1 ((NPOS + TPB1 - 1)/TPB1)    /* 118 */
#define SMEM_B1_BYTES (LLL * KV_PITCH * 4)
__global__ void __launch_bounds__(256, 2)
kernelB1() {
    extern __shared__ float kvs[];   // kv[l][h][x][y], per-l pitch KV_PITCH

    int b = blockIdx.y;
    int P = blockIdx.x * TPB1 + threadIdx.x;
    int tid = threadIdx.x;

    const float* kvb = g_kv + (size_t)b * (LLL * HEAD * DKK * DKK);
    for (int i = tid; i < LLL * HEAD * DKK * DKK; i += 256) {
        int l = i >> 11, rr = i & 2047;
        kvs[l * KV_PITCH + rr] = kvb[i];
    }
    __syncthreads();

    if (P >= NPOS) return;
    int l = P % 12;
    const float* kvl = kvs + l * KV_PITCH;
    const float* qb = g_q + ((size_t)b * CC) * NPOS + P;
    float* ob = g_o + ((size_t)b * CC) * NPOS + P;

#pragma unroll
    for (int h = 0; h < HEAD; h++) {
        const float* kvh = kvl + h * 256;
        float s16[16];
#pragma unroll
        for (int y = 0; y < 16; y++) s16[y] = 0.f;
#pragma unroll
        for (int xq = 0; xq < 16; xq++) {
            float qv = qb[(size_t)(h * 16 + xq) * NPOS];
            const float4* kr = (const float4*)(kvh + xq * 16);
            float4 k0 = kr[0], k1 = kr[1], k2 = kr[2], k3 = kr[3];
            s16[0]  = fmaf(qv, k0.x, s16[0]);  s16[1]  = fmaf(qv, k0.y, s16[1]);
            s16[2]  = fmaf(qv, k0.z, s16[2]);  s16[3]  = fmaf(qv, k0.w, s16[3]);
            s16[4]  = fmaf(qv, k1.x, s16[4]);  s16[5]  = fmaf(qv, k1.y, s16[5]);
            s16[6]  = fmaf(qv, k1.z, s16[6]);  s16[7]  = fmaf(qv, k1.w, s16[7]);
            s16[8]  = fmaf(qv, k2.x, s16[8]);  s16[9]  = fmaf(qv, k2.y, s16[9]);
            s16[10] = fmaf(qv, k2.z, s16[10]); s16[11] = fmaf(qv, k2.w, s16[11]);
            s16[12] = fmaf(qv, k3.x, s16[12]); s16[13] = fmaf(qv, k3.y, s16[13]);
            s16[14] = fmaf(qv, k3.z, s16[14]); s16[15] = fmaf(qv, k3.w, s16[15]);
        }
#pragma unroll
        for (int y = 0; y < 16; y++) ob[(size_t)(h * 16 + y) * NPOS] = s16[y];
    }
}

// ---------------- pass B2: out = relu(Wc o + bc) ----------------
#define SMEM_B2_BYTES (16384 * 4)
__global__ void __launch_bounds__(256, 2)
kernelB2(const float* __restrict__ bc, float* __restrict__ out) {
    extern __shared__ float os[];   // [c][p]

    int b = blockIdx.y, tile = blockIdx.x;
    int p0 = tile * TP;
    int pc = min(TP, NPOS - p0);
    int tid = threadIdx.x;

    const float* ob0 = g_o + ((size_t)b * CC) * NPOS + p0;
    if (pc == TP) {
        for (int i = tid; i < CC * TP / 4; i += 256) {
            int c = i >> 5, p4 = i & 31;
            ((float4*)os)[c*32 + p4] = ((const float4*)(ob0 + (size_t)c * NPOS))[p4];
        }
    } else {
        for (int i = tid; i < CC * TP; i += 256) {
            int c = i >> 7, p = i & 127;
            os[i] = (p < pc) ? ob0[(size_t)c * NPOS + p] : 0.f;
        }
    }
    __syncthreads();

    int ty = tid >> 4, tx = tid & 15;
    int o0 = ty * 8, pt = tx * 8;
    u64 acc[8][4];
    gemm128g(g_WcT, os, acc, o0, pt);

    float* ob = out + ((size_t)b * CC) * NPOS + p0;
    if (pc == TP) {
#pragma unroll
        for (int j = 0; j < 8; j++) {
            float bj = __ldg(bc + o0 + j);
            float* row = ob + (size_t)(o0 + j) * NPOS + pt;
            float2 f0 = unpack2(acc[j][0]), f1 = unpack2(acc[j][1]);
            float2 f2 = unpack2(acc[j][2]), f3 = unpack2(acc[j][3]);
            ((float4*)row)[0] = make_float4(fmaxf(f0.x + bj, 0.f), fmaxf(f0.y + bj, 0.f),
                                            fmaxf(f1.x + bj, 0.f), fmaxf(f1.y + bj, 0.f));
            ((float4*)row)[1] = make_float4(fmaxf(f2.x + bj, 0.f), fmaxf(f2.y + bj, 0.f),
                                            fmaxf(f3.x + bj, 0.f), fmaxf(f3.y + bj, 0.f));
        }
    } else {
#pragma unroll
        for (int j = 0; j < 8; j++) {
            float bj = __ldg(bc + o0 + j);
            float* row = ob + (size_t)(o0 + j) * NPOS;
#pragma unroll
            for (int i = 0; i < 4; i++) {
                float2 f = unpack2(acc[j][i]);
                int pA = pt + 2*i, pB = pt + 2*i + 1;
                if (pA < pc) row[pA] = fmaxf(f.x + bj, 0.f);
                if (pB < pc) row[pB] = fmaxf(f.y + bj, 0.f);
            }
        }
    }
}

// ---------------- launch ----------------
extern "C" void kernel_launch(void* const* d_in, const int* in_sizes, int n_in,
                              void* d_out, int out_size) {
    (void)in_sizes; (void)n_in; (void)out_size;
    const float* x      = (const float*)d_in[0];
    const float* Wq     = (const float*)d_in[1];
    const float* bq     = (const float*)d_in[2];
    const float* Wv     = (const float*)d_in[3];
    const float* bv     = (const float*)d_in[4];
    const float* Wc     = (const float*)d_in[5];
    const float* bc     = (const float*)d_in[6];
    const float* s_bank = (const float*)d_in[7];
    float* out = (float*)d_out;

    cudaFuncSetAttribute(kernelA,  cudaFuncAttributeMaxDynamicSharedMemorySize, SMEM_A_BYTES);
    cudaFuncSetAttribute(kernelB1, cudaFuncAttributeMaxDynamicSharedMemorySize, SMEM_B1_BYTES);
    cudaFuncSetAttribute(kernelB2, cudaFuncAttributeMaxDynamicSharedMemorySize, SMEM_B2_BYTES);

    k_prep_w<<<3, 256>>>(Wq, Wv, Wc);
    k_key<<<(HEAD*LLL*NNN + 255) / 256, 256>>>(s_bank);
    k_zero_kv<<<(BB*LLL*HEAD*DKK*DKK/4) / 256, 256>>>();
    kernelA<<<dim3(NT, BB), 256, SMEM_A_BYTES>>>(x, bq, bv);
    kernelB1<<<dim3(NTB1, BB), 256, SMEM_B1_BYTES>>>();
    kernelB2<<<dim3(NT, BB), 256, SMEM_B2_BYTES>>>(bc, out);
}